// round 15
// baseline (speedup 1.0000x reference)
#include <cuda_runtime.h>
#include <math.h>
#include <cstdint>

#define BATCH 256
#define NBOX 98
#define KTOP 10

// ---------------- scratch (static device globals; no allocation) ----------------
// Activation operands stored as bf16x2 hi/lo planes (same bytes as fp32):
// plane[row][j] = {bf16(a[row][2j]) in low half, bf16(a[row][2j+1]) in high half}
__device__ uint32_t g_A0h[12544 * 640], g_A0l[12544 * 640];   // gathered input
__device__ uint32_t g_a1h[256 * 3136],  g_a1l[256 * 3136];    // act1 (fc1 A)
__device__ uint32_t g_h1h[256 * 2048],  g_h1l[256 * 2048];    // h1 (fc2 A)
__device__ float g_part[3 * 12544 * 128];  // split-K partials (max: conv)
__device__ float g_h2[BATCH * 1470];
__device__ float g_boxes[BATCH * NBOX * 4];
__device__ float g_conf[BATCH * NBOX];
__device__ int   g_labels[BATCH * NBOX];

// ---------------- helpers -------------------------------------------------------
__device__ __forceinline__ uint32_t smem_u32(const void* p) {
    uint32_t a;
    asm("{ .reg .u64 t; cvta.to.shared.u64 t, %1; cvt.u32.u64 %0, t; }"
        : "=r"(a) : "l"(p));
    return a;
}
__device__ __forceinline__ void cp4(uint32_t dst, const void* src) {
    asm volatile("cp.async.ca.shared.global [%0], [%1], 4;" :: "r"(dst), "l"(src));
}
__device__ __forceinline__ void cp8(uint32_t dst, const void* src) {
    asm volatile("cp.async.ca.shared.global [%0], [%1], 8;" :: "r"(dst), "l"(src));
}
#define CP_COMMIT() asm volatile("cp.async.commit_group;" ::: "memory")
#define CP_WAIT2()  asm volatile("cp.async.wait_group 2;" ::: "memory")

// ---- 3xBF16 split helpers (hi = truncate to bf16; lo = rn-bf16(a - hi)) ----
__device__ __forceinline__ float sub_hi(float a) {
    return a - __uint_as_float(__float_as_uint(a) & 0xFFFF0000u);
}
__device__ __forceinline__ uint32_t prmt_hi(uint32_t x, uint32_t y) {
    uint32_t r;
    asm("prmt.b32 %0, %1, %2, 0x7632;" : "=r"(r) : "r"(x), "r"(y));
    return r;
}
__device__ __forceinline__ uint32_t cvt_bf16x2(float h, float l) {
    uint32_t r;
    asm("cvt.rn.bf16x2.f32 %0, %1, %2;" : "=r"(r) : "f"(h), "f"(l));
    return r;
}
// produce the pair words for elements (a0 = even k, a1 = odd k)
__device__ __forceinline__ void pack_pair(float a0, float a1,
                                          uint32_t& hi, uint32_t& lo) {
    hi = prmt_hi(__float_as_uint(a0), __float_as_uint(a1));
    lo = cvt_bf16x2(sub_hi(a1), sub_hi(a0));
}

__device__ __forceinline__ void mma_bf16(float* c, uint32_t a0, uint32_t a1,
                                         uint32_t a2, uint32_t a3,
                                         uint32_t b0, uint32_t b1) {
    asm volatile(
        "mma.sync.aligned.m16n8k16.row.col.f32.bf16.bf16.f32 "
        "{%0,%1,%2,%3}, {%4,%5,%6,%7}, {%8,%9}, {%0,%1,%2,%3};"
        : "+f"(c[0]), "+f"(c[1]), "+f"(c[2]), "+f"(c[3])
        : "r"(a0), "r"(a1), "r"(a2), "r"(a3), "r"(b0), "r"(b1));
}

// ---------------- gather: x[:, :, ::2, ::2] -> A0 planes -------------------------
__global__ void gather_kernel(const float* __restrict__ x) {
    __shared__ float tile[64][50];
    const int b  = blockIdx.y;
    const int c0 = blockIdx.x * 64;
    const int t  = threadIdx.x;
    for (int lin = t; lin < 64 * 49; lin += 256) {
        int c = lin / 49, hw = lin % 49;
        tile[c][hw] =
            x[((size_t)(b * 1280 + c0 + c) * 14 + (hw / 7) * 2) * 14 + (hw % 7) * 2];
    }
    __syncthreads();
    for (int lin = t; lin < 32 * 49; lin += 256) {
        int hw = lin >> 5, jl = lin & 31;
        uint32_t hi, lo;
        pack_pair(tile[2 * jl][hw], tile[2 * jl + 1][hw], hi, lo);
        size_t w = ((size_t)b * 49 + hw) * 640 + (c0 >> 1) + jl;
        g_A0h[w] = hi;
        g_A0l[w] = lo;
    }
}

// ---------------- 3xBF16 mma.sync GEMM, pre-split A planes, BK=16, 4 stages ------
// CTA tile 128x128; 8 warps: 2(m) x 4(n); warp tile 64x32.
// smem stage (4096 words): A-hi [0,1024), A-lo [1024,2048), B raw fp32 [2048,4096).
// A seg s (s=0..15, 8 rows each): word s*64 + lane*2 + {0,1} = pairs j=tig, tig+4.
// B seg layout unchanged: seg*128 + lane*4, k = {2tig,2tig+1,2tig+8,2tig+9}.
#define STAGE_WORDS 4096
#define DSMEM_BYTES (4 * STAGE_WORDS * 4)

__device__ __forceinline__ void load_stage(
    uint32_t su, int buf,
    const uint32_t* __restrict__ Ah, const uint32_t* __restrict__ Al,
    const float* __restrict__ B,
    int Kp, int K, const int* rowA, const int* rowB, int kb,
    int wid, int lane, int tig)
{
    uint32_t base = su + buf * (STAGE_WORDS * 4);
    const int jb = kb >> 1;
#pragma unroll
    for (int i = 0; i < 2; i++) {
        int seg = wid + i * 8;
        uint32_t da = base + (uint32_t)(seg * 64 + lane * 2) * 4;
        const uint32_t* sah = Ah + (size_t)rowA[i] * Kp + jb;
        const uint32_t* sal = Al + (size_t)rowA[i] * Kp + jb;
        cp4(da,            sah + tig);
        cp4(da + 4,        sah + tig + 4);
        cp4(da + 4096,     sal + tig);
        cp4(da + 4100,     sal + tig + 4);
        uint32_t db = base + (uint32_t)(2048 + seg * 128 + lane * 4) * 4;
        const float* sb = B + (size_t)rowB[i] * K + kb + 2 * tig;
        cp8(db,     sb);
        cp8(db + 8, sb + 8);
    }
}

__global__ void __launch_bounds__(256, 2)
gemm_mma(const uint32_t* __restrict__ Ah, const uint32_t* __restrict__ Al,
         const float* __restrict__ B,
         float* __restrict__ P, int M, int N, int K, int kc, int Npad) {
    extern __shared__ __align__(16) uint32_t sm[];
    const uint32_t su = smem_u32(sm);

    const int tid  = threadIdx.x;
    const int wid  = tid >> 5;
    const int lane = tid & 31;
    const int g    = lane >> 2;
    const int tig  = lane & 3;
    const int wm   = wid >> 2;
    const int wn   = wid & 3;

    const int Kp = K >> 1;
    const int m0 = blockIdx.y * 128;
    const int n0 = blockIdx.x * 128;
    const int k0 = blockIdx.z * kc;
    const int nstages = (min(kc, K - k0)) >> 4;

    int rowA[2], rowB[2];
#pragma unroll
    for (int i = 0; i < 2; i++) {
        int sA = wid + i * 8;
        rowA[i] = m0 + (sA >> 1) * 16 + (sA & 1) * 8 + g;
        int nr = n0 + (wid + i * 8) * 8 + g;
        rowB[i] = (nr < N) ? nr : (N - 1);
    }

    float acc[4][4][4];
#pragma unroll
    for (int a = 0; a < 4; a++)
#pragma unroll
        for (int b = 0; b < 4; b++)
#pragma unroll
            for (int c = 0; c < 4; c++) acc[a][b][c] = 0.f;

    // prologue: issue stages 0..2
#pragma unroll
    for (int s = 0; s < 3; s++) {
        if (s < nstages) load_stage(su, s, Ah, Al, B, Kp, K, rowA, rowB,
                                    k0 + s * 16, wid, lane, tig);
        CP_COMMIT();
    }

    for (int t = 0; t < nstages; t++) {
        CP_WAIT2();
        __syncthreads();
        if (t + 3 < nstages)
            load_stage(su, (t + 3) & 3, Ah, Al, B, Kp, K, rowA, rowB,
                       k0 + (t + 3) * 16, wid, lane, tig);
        CP_COMMIT();

        const uint32_t* sb = sm + (t & 3) * STAGE_WORDS;

        // ---- B fragments: raw fp32 -> hi via PRMT, lo via FADD+CVT ----
        uint32_t Bh[4][2], Bl[4][2];
#pragma unroll
        for (int nt = 0; nt < 4; nt++) {
            uint4 raw = *(const uint4*)&sb[2048 + (wn * 4 + nt) * 128 + lane * 4];
            const float* f = (const float*)&raw;
            const uint32_t* u = (const uint32_t*)&raw;
            Bh[nt][0] = prmt_hi(u[0], u[1]);
            Bh[nt][1] = prmt_hi(u[2], u[3]);
            Bl[nt][0] = cvt_bf16x2(sub_hi(f[1]), sub_hi(f[0]));
            Bl[nt][1] = cvt_bf16x2(sub_hi(f[3]), sub_hi(f[2]));
        }

#pragma unroll
        for (int mt = 0; mt < 4; mt++) {
            int s0 = (wm * 4 + mt) * 2;
            // A fragments: direct LDS.64 from planes, zero ALU
            uint2 h0 = *(const uint2*)&sb[s0 * 64 + lane * 2];          // row g
            uint2 h1 = *(const uint2*)&sb[(s0 + 1) * 64 + lane * 2];    // row g+8
            uint2 l0 = *(const uint2*)&sb[1024 + s0 * 64 + lane * 2];
            uint2 l1 = *(const uint2*)&sb[1024 + (s0 + 1) * 64 + lane * 2];
#pragma unroll
            for (int nt = 0; nt < 4; nt++) {
                float* c = acc[mt][nt];
                mma_bf16(c, h0.x, h1.x, h0.y, h1.y, Bh[nt][0], Bh[nt][1]);
                mma_bf16(c, l0.x, l1.x, l0.y, l1.y, Bh[nt][0], Bh[nt][1]);
                mma_bf16(c, h0.x, h1.x, h0.y, h1.y, Bl[nt][0], Bl[nt][1]);
            }
        }
    }

    // ---- epilogue: write partials ----
    float* Pz = P + (size_t)blockIdx.z * M * Npad;
    const int mbase = m0 + wm * 64;
    const int nbase = n0 + wn * 32;
#pragma unroll
    for (int mt = 0; mt < 4; mt++) {
#pragma unroll
        for (int nt = 0; nt < 4; nt++) {
            float* c = acc[mt][nt];
            int r = mbase + mt * 16 + g;
            int cc = nbase + nt * 8 + tig * 2;
            *(float2*)&Pz[(size_t)r * Npad + cc]       = make_float2(c[0], c[1]);
            *(float2*)&Pz[(size_t)(r + 8) * Npad + cc] = make_float2(c[2], c[3]);
        }
    }
}

// ---------------- split-K reduces with fused epilogues + plane writes -----------
// conv: act1 logical row b (256), col k = col*49 + hw (6272). One thread per
// (b, pair j): k0=2j, k1=2j+1.
__global__ void reduce_conv(const float* __restrict__ part,
                            const float* __restrict__ bias) {
    int idx = blockIdx.x * blockDim.x + threadIdx.x;
    if (idx >= 256 * 3136) return;
    const int S = 12544 * 128;
    int b = idx >> 11;          // /2048? no: 3136 per b
    b = idx / 3136;
    int j = idx - b * 3136;
    float v[2];
#pragma unroll
    for (int e = 0; e < 2; e++) {
        int k = 2 * j + e;
        int col = k / 49, hw = k - col * 49;
        int m = b * 49 + hw;
        int p = m * 128 + col;
        v[e] = part[p] + part[S + p] + part[2 * S + p] + bias[col];
    }
    uint32_t hi, lo;
    pack_pair(v[0], v[1], hi, lo);
    g_a1h[idx] = hi;
    g_a1l[idx] = lo;
}

__global__ void reduce_fc1(const float* __restrict__ part,
                           const float* __restrict__ bias) {
    int idx = blockIdx.x * blockDim.x + threadIdx.x;
    if (idx >= 256 * 2048) return;
    const int S = 256 * 4096;
    int m = idx >> 11;
    int j = idx & 2047;
    int p = (m << 12) + 2 * j;
    float v[2];
#pragma unroll
    for (int e = 0; e < 2; e++) {
        float s = part[p + e] + part[S + p + e] + part[2 * S + p + e]
                + part[3 * S + p + e] + bias[2 * j + e];
        v[e] = (s >= 0.f) ? s : 0.1f * s;
    }
    uint32_t hi, lo;
    pack_pair(v[0], v[1], hi, lo);
    g_h1h[idx] = hi;
    g_h1l[idx] = lo;
}

__global__ void reduce_fc2(const float* __restrict__ part,
                           const float* __restrict__ bias) {
    int idx = blockIdx.x * blockDim.x + threadIdx.x;
    if (idx >= 256 * 1470) return;
    int m = idx / 1470, n = idx - m * 1470;
    float v = 0.f;
#pragma unroll
    for (int s = 0; s < 12; s++) v += part[(size_t)s * 256 * 1536 + m * 1536 + n];
    v += bias[n];
    g_h2[idx] = 1.f / (1.f + expf(-v));
}

// ---------------- decode: h2 -> boxes / conf / labels ---------------------------
__global__ void decode_kernel() {
    int idx = blockIdx.x * blockDim.x + threadIdx.x;
    if (idx >= BATCH * NBOX) return;
    int b = idx / NBOX, n = idx % NBOX;
    int cell = n >> 1;
    int gi = cell / 7, gj = cell % 7;
    const float* h = g_h2 + (size_t)b * 1470;

    float bx = h[n * 4 + 0], by = h[n * 4 + 1];
    float bw = h[n * 4 + 2], bh = h[n * 4 + 3];
    float cx = bx * 64.f + gi * 64.f;
    float cy = by * 64.f + gj * 64.f;
    float w  = bw * 448.f;
    float hh = bh * 448.f;
    float x1 = fminf(fmaxf(cx - 0.5f * w,  0.f), 448.f);
    float y1 = fminf(fmaxf(cy - 0.5f * hh, 0.f), 448.f);
    float x2 = fminf(fmaxf(cx + 0.5f * w,  0.f), 448.f);
    float y2 = fminf(fmaxf(cy + 0.5f * hh, 0.f), 448.f);

    g_boxes[idx * 4 + 0] = x1;
    g_boxes[idx * 4 + 1] = y1;
    g_boxes[idx * 4 + 2] = x2;
    g_boxes[idx * 4 + 3] = y2;
    g_conf[idx] = h[392 + n];

    const float* cl = h + 490 + cell * 20;
    float best = cl[0];
    int lab = 0;
#pragma unroll
    for (int c = 1; c < 20; c++) {
        float v = cl[c];
        if (v > best) { best = v; lab = c; }  // first max wins (matches jnp.argmax)
    }
    g_labels[idx] = lab;
}

// ---------------- NMS: one block per image --------------------------------------
__global__ void __launch_bounds__(128)
nms_kernel(float* __restrict__ out, int out_size) {
    int b = blockIdx.x;
    int t = threadIdx.x;

    __shared__ float sc[NBOX], sx1[NBOX], sy1[NBOX], sx2[NBOX], sy2[NBOX];
    __shared__ int   sl[NBOX], order[NBOX];
    __shared__ float oc[NBOX], ox1[NBOX], oy1[NBOX], ox2[NBOX], oy2[NBOX], oarea[NBOX];
    __shared__ int   ol[NBOX];
    __shared__ unsigned char keep[NBOX];

    if (t < NBOX) {
        int g = b * NBOX + t;
        sc[t]  = g_conf[g];
        sl[t]  = g_labels[g];
        sx1[t] = g_boxes[g * 4 + 0];
        sy1[t] = g_boxes[g * 4 + 1];
        sx2[t] = g_boxes[g * 4 + 2];
        sy2[t] = g_boxes[g * 4 + 3];
    }
    __syncthreads();

    if (t < NBOX) {
        float c = sc[t];
        int r = 0;
        for (int j = 0; j < NBOX; j++) {
            float cj = sc[j];
            r += (cj > c) || (cj == c && j < t);
        }
        order[r] = t;
    }
    __syncthreads();

    if (t < NBOX) {
        int s = order[t];
        oc[t] = sc[s];  ol[t] = sl[s];
        ox1[t] = sx1[s]; oy1[t] = sy1[s];
        ox2[t] = sx2[s]; oy2[t] = sy2[s];
        oarea[t] = fmaxf(ox2[t] - ox1[t], 0.f) * fmaxf(oy2[t] - oy1[t], 0.f);
        keep[t] = (oc[t] > 0.1f) ? (unsigned char)1 : (unsigned char)0;
    }
    __syncthreads();

    for (int i = 0; i < NBOX; i++) {
        if (keep[i] && t < NBOX && t > i) {
            float ix1 = fmaxf(ox1[i], ox1[t]);
            float iy1 = fmaxf(oy1[i], oy1[t]);
            float ix2 = fminf(ox2[i], ox2[t]);
            float iy2 = fminf(oy2[i], oy2[t]);
            float inter = fmaxf(ix2 - ix1, 0.f) * fmaxf(iy2 - iy1, 0.f);
            float uni = oarea[i] + oarea[t] - inter;
            float iou = (uni > 0.f) ? (inter / uni) : 0.f;
            if (iou > 0.7f) keep[t] = 0;
        }
        __syncthreads();
    }

    if (t == 0) {
        unsigned char used[NBOX];
        for (int j = 0; j < NBOX; j++) used[j] = 0;
        const int BK4 = BATCH * KTOP * 4;
        const int BK  = BATCH * KTOP;
        for (int k = 0; k < KTOP; k++) {
            float best = -2.f;
            int bi = 0;
            for (int j = 0; j < NBOX; j++) {
                if (used[j]) continue;
                float s = keep[j] ? oc[j] : -1.0f;
                if (s > best) { best = s; bi = j; }
            }
            used[bi] = 1;
            bool valid = best > 0.1f;
            int ob = (b * KTOP + k) * 4;
            if (ob + 3 < out_size) {
                out[ob + 0] = valid ? ox1[bi] : 0.f;
                out[ob + 1] = valid ? oy1[bi] : 0.f;
                out[ob + 2] = valid ? ox2[bi] : 0.f;
                out[ob + 3] = valid ? oy2[bi] : 0.f;
            }
            int ol_idx = BK4 + b * KTOP + k;
            if (ol_idx < out_size) out[ol_idx] = valid ? (float)ol[bi] : 0.f;
            int oc_idx = BK4 + BK + b * KTOP + k;
            if (oc_idx < out_size) out[oc_idx] = valid ? oc[bi] : 0.f;
        }
    }
}

// ---------------- launch ---------------------------------------------------------
extern "C" void kernel_launch(void* const* d_in, const int* in_sizes, int n_in,
                              void* d_out, int out_size) {
    const float* x      = (const float*)d_in[0];
    const float* conv_w = (const float*)d_in[1];
    const float* conv_b = (const float*)d_in[2];
    const float* fc1_w  = (const float*)d_in[3];
    const float* fc1_b  = (const float*)d_in[4];
    const float* fc2_w  = (const float*)d_in[5];
    const float* fc2_b  = (const float*)d_in[6];
    float* out = (float*)d_out;

    uint32_t *A0h, *A0l, *a1h, *a1l, *h1h, *h1l;
    float *part;
    cudaGetSymbolAddress((void**)&A0h, g_A0h);
    cudaGetSymbolAddress((void**)&A0l, g_A0l);
    cudaGetSymbolAddress((void**)&a1h, g_a1h);
    cudaGetSymbolAddress((void**)&a1l, g_a1l);
    cudaGetSymbolAddress((void**)&h1h, g_h1h);
    cudaGetSymbolAddress((void**)&h1l, g_h1l);
    cudaGetSymbolAddress((void**)&part, g_part);

    cudaFuncSetAttribute(gemm_mma, cudaFuncAttributeMaxDynamicSharedMemorySize,
                         DSMEM_BYTES);

    // 1. gather subsampled input -> A0 bf16x2 hi/lo planes
    gather_kernel<<<dim3(20, 256), 256>>>(x);

    // 2. conv GEMM: (12544 x 1280) * (128 x 1280)^T, split-K=3 -> 294 CTAs
    gemm_mma<<<dim3(1, 98, 3), 256, DSMEM_BYTES>>>(A0h, A0l, conv_w, part,
                                                   12544, 128, 1280, 432, 128);
    reduce_conv<<<(256 * 3136 + 255) / 256, 256>>>(part, conv_b);

    // 3. fc1 GEMM: (256 x 6272) * (4096 x 6272)^T, split-K=4 -> 256 CTAs
    gemm_mma<<<dim3(32, 2, 4), 256, DSMEM_BYTES>>>(a1h, a1l, fc1_w, part,
                                                   256, 4096, 6272, 1568, 4096);
    reduce_fc1<<<(256 * 2048 + 255) / 256, 256>>>(part, fc1_b);

    // 4. fc2 GEMM: (256 x 4096) * (1470 x 4096)^T, split-K=12 -> 288 CTAs
    gemm_mma<<<dim3(12, 2, 12), 256, DSMEM_BYTES>>>(h1h, h1l, fc2_w, part,
                                                    256, 1470, 4096, 352, 1536);
    reduce_fc2<<<(256 * 1470 + 255) / 256, 256>>>(part, fc2_b);

    // 5. decode + NMS
    decode_kernel<<<(BATCH * NBOX + 255) / 256, 256>>>();
    nms_kernel<<<BATCH, 128>>>(out, out_size);
}

// round 16
// speedup vs baseline: 1.0001x; 1.0001x over previous
#include <cuda_runtime.h>
#include <math.h>
#include <cstdint>

#define BATCH 256
#define NBOX 98
#define KTOP 10

// ---------------- scratch (static device globals; no allocation) ----------------
// Activation operands stored as bf16x2 hi/lo planes (same bytes as fp32):
// plane[row][j] = {bf16(a[row][2j]) in low half, bf16(a[row][2j+1]) in high half}
__device__ uint32_t g_A0h[12544 * 640], g_A0l[12544 * 640];   // gathered input
__device__ uint32_t g_a1h[256 * 3136],  g_a1l[256 * 3136];    // act1 (fc1 A)
__device__ uint32_t g_h1h[256 * 2048],  g_h1l[256 * 2048];    // h1 (fc2 A)
__device__ float g_part[3 * 12544 * 128];  // split-K partials (max: conv)
__device__ float g_h2[BATCH * 1470];
__device__ float g_boxes[BATCH * NBOX * 4];
__device__ float g_conf[BATCH * NBOX];
__device__ int   g_labels[BATCH * NBOX];

// ---------------- helpers -------------------------------------------------------
__device__ __forceinline__ uint32_t smem_u32(const void* p) {
    uint32_t a;
    asm("{ .reg .u64 t; cvta.to.shared.u64 t, %1; cvt.u32.u64 %0, t; }"
        : "=r"(a) : "l"(p));
    return a;
}
__device__ __forceinline__ void cp4(uint32_t dst, const void* src) {
    asm volatile("cp.async.ca.shared.global [%0], [%1], 4;" :: "r"(dst), "l"(src));
}
__device__ __forceinline__ void cp8(uint32_t dst, const void* src) {
    asm volatile("cp.async.ca.shared.global [%0], [%1], 8;" :: "r"(dst), "l"(src));
}
#define CP_COMMIT() asm volatile("cp.async.commit_group;" ::: "memory")
#define CP_WAIT2()  asm volatile("cp.async.wait_group 2;" ::: "memory")

// ---- 3xBF16 split helpers (hi = truncate to bf16; lo = rn-bf16(a - hi)) ----
__device__ __forceinline__ float sub_hi(float a) {
    return a - __uint_as_float(__float_as_uint(a) & 0xFFFF0000u);
}
__device__ __forceinline__ uint32_t prmt_hi(uint32_t x, uint32_t y) {
    uint32_t r;
    asm("prmt.b32 %0, %1, %2, 0x7632;" : "=r"(r) : "r"(x), "r"(y));
    return r;
}
__device__ __forceinline__ uint32_t cvt_bf16x2(float h, float l) {
    uint32_t r;
    asm("cvt.rn.bf16x2.f32 %0, %1, %2;" : "=r"(r) : "f"(h), "f"(l));
    return r;
}
// produce the pair words for elements (a0 = even k, a1 = odd k)
__device__ __forceinline__ void pack_pair(float a0, float a1,
                                          uint32_t& hi, uint32_t& lo) {
    hi = prmt_hi(__float_as_uint(a0), __float_as_uint(a1));
    lo = cvt_bf16x2(sub_hi(a1), sub_hi(a0));
}

__device__ __forceinline__ void mma_bf16(float* c, uint32_t a0, uint32_t a1,
                                         uint32_t a2, uint32_t a3,
                                         uint32_t b0, uint32_t b1) {
    asm volatile(
        "mma.sync.aligned.m16n8k16.row.col.f32.bf16.bf16.f32 "
        "{%0,%1,%2,%3}, {%4,%5,%6,%7}, {%8,%9}, {%0,%1,%2,%3};"
        : "+f"(c[0]), "+f"(c[1]), "+f"(c[2]), "+f"(c[3])
        : "r"(a0), "r"(a1), "r"(a2), "r"(a3), "r"(b0), "r"(b1));
}

// ---------------- gather: x[:, :, ::2, ::2] -> A0 planes -------------------------
__global__ void gather_kernel(const float* __restrict__ x) {
    __shared__ float tile[64][50];
    const int b  = blockIdx.y;
    const int c0 = blockIdx.x * 64;
    const int t  = threadIdx.x;
    for (int lin = t; lin < 64 * 49; lin += 256) {
        int c = lin / 49, hw = lin % 49;
        tile[c][hw] =
            x[((size_t)(b * 1280 + c0 + c) * 14 + (hw / 7) * 2) * 14 + (hw % 7) * 2];
    }
    __syncthreads();
    for (int lin = t; lin < 32 * 49; lin += 256) {
        int hw = lin >> 5, jl = lin & 31;
        uint32_t hi, lo;
        pack_pair(tile[2 * jl][hw], tile[2 * jl + 1][hw], hi, lo);
        size_t w = ((size_t)b * 49 + hw) * 640 + (c0 >> 1) + jl;
        g_A0h[w] = hi;
        g_A0l[w] = lo;
    }
}

// ---------------- 3xBF16 mma.sync GEMM, pre-split A planes, BK=16, 4 stages ------
// CTA tile 128x128; 8 warps: 2(m) x 4(n); warp tile 64x32.
// smem stage (4096 words): A-hi [0,1024), A-lo [1024,2048), B raw fp32 [2048,4096).
// A seg s (s=0..15, 8 rows each): word s*64 + lane*2 + {0,1} = pairs j=tig, tig+4.
// B seg layout unchanged: seg*128 + lane*4, k = {2tig,2tig+1,2tig+8,2tig+9}.
#define STAGE_WORDS 4096
#define DSMEM_BYTES (4 * STAGE_WORDS * 4)

__device__ __forceinline__ void load_stage(
    uint32_t su, int buf,
    const uint32_t* __restrict__ Ah, const uint32_t* __restrict__ Al,
    const float* __restrict__ B,
    int Kp, int K, const int* rowA, const int* rowB, int kb,
    int wid, int lane, int tig)
{
    uint32_t base = su + buf * (STAGE_WORDS * 4);
    const int jb = kb >> 1;
#pragma unroll
    for (int i = 0; i < 2; i++) {
        int seg = wid + i * 8;
        uint32_t da = base + (uint32_t)(seg * 64 + lane * 2) * 4;
        const uint32_t* sah = Ah + (size_t)rowA[i] * Kp + jb;
        const uint32_t* sal = Al + (size_t)rowA[i] * Kp + jb;
        cp4(da,            sah + tig);
        cp4(da + 4,        sah + tig + 4);
        cp4(da + 4096,     sal + tig);
        cp4(da + 4100,     sal + tig + 4);
        uint32_t db = base + (uint32_t)(2048 + seg * 128 + lane * 4) * 4;
        const float* sb = B + (size_t)rowB[i] * K + kb + 2 * tig;
        cp8(db,     sb);
        cp8(db + 8, sb + 8);
    }
}

__global__ void __launch_bounds__(256, 2)
gemm_mma(const uint32_t* __restrict__ Ah, const uint32_t* __restrict__ Al,
         const float* __restrict__ B,
         float* __restrict__ P, int M, int N, int K, int kc, int Npad) {
    extern __shared__ __align__(16) uint32_t sm[];
    const uint32_t su = smem_u32(sm);

    const int tid  = threadIdx.x;
    const int wid  = tid >> 5;
    const int lane = tid & 31;
    const int g    = lane >> 2;
    const int tig  = lane & 3;
    const int wm   = wid >> 2;
    const int wn   = wid & 3;

    const int Kp = K >> 1;
    const int m0 = blockIdx.y * 128;
    const int n0 = blockIdx.x * 128;
    const int k0 = blockIdx.z * kc;
    const int nstages = (min(kc, K - k0)) >> 4;

    int rowA[2], rowB[2];
#pragma unroll
    for (int i = 0; i < 2; i++) {
        int sA = wid + i * 8;
        rowA[i] = m0 + (sA >> 1) * 16 + (sA & 1) * 8 + g;
        int nr = n0 + (wid + i * 8) * 8 + g;
        rowB[i] = (nr < N) ? nr : (N - 1);
    }

    float acc[4][4][4];
#pragma unroll
    for (int a = 0; a < 4; a++)
#pragma unroll
        for (int b = 0; b < 4; b++)
#pragma unroll
            for (int c = 0; c < 4; c++) acc[a][b][c] = 0.f;

    // prologue: issue stages 0..2
#pragma unroll
    for (int s = 0; s < 3; s++) {
        if (s < nstages) load_stage(su, s, Ah, Al, B, Kp, K, rowA, rowB,
                                    k0 + s * 16, wid, lane, tig);
        CP_COMMIT();
    }

    for (int t = 0; t < nstages; t++) {
        CP_WAIT2();
        __syncthreads();
        if (t + 3 < nstages)
            load_stage(su, (t + 3) & 3, Ah, Al, B, Kp, K, rowA, rowB,
                       k0 + (t + 3) * 16, wid, lane, tig);
        CP_COMMIT();

        const uint32_t* sb = sm + (t & 3) * STAGE_WORDS;

        // ---- B fragments: raw fp32 -> hi via PRMT, lo via FADD+CVT ----
        uint32_t Bh[4][2], Bl[4][2];
#pragma unroll
        for (int nt = 0; nt < 4; nt++) {
            uint4 raw = *(const uint4*)&sb[2048 + (wn * 4 + nt) * 128 + lane * 4];
            const float* f = (const float*)&raw;
            const uint32_t* u = (const uint32_t*)&raw;
            Bh[nt][0] = prmt_hi(u[0], u[1]);
            Bh[nt][1] = prmt_hi(u[2], u[3]);
            Bl[nt][0] = cvt_bf16x2(sub_hi(f[1]), sub_hi(f[0]));
            Bl[nt][1] = cvt_bf16x2(sub_hi(f[3]), sub_hi(f[2]));
        }

#pragma unroll
        for (int mt = 0; mt < 4; mt++) {
            int s0 = (wm * 4 + mt) * 2;
            // A fragments: direct LDS.64 from planes, zero ALU
            uint2 h0 = *(const uint2*)&sb[s0 * 64 + lane * 2];          // row g
            uint2 h1 = *(const uint2*)&sb[(s0 + 1) * 64 + lane * 2];    // row g+8
            uint2 l0 = *(const uint2*)&sb[1024 + s0 * 64 + lane * 2];
            uint2 l1 = *(const uint2*)&sb[1024 + (s0 + 1) * 64 + lane * 2];
#pragma unroll
            for (int nt = 0; nt < 4; nt++) {
                float* c = acc[mt][nt];
                mma_bf16(c, h0.x, h1.x, h0.y, h1.y, Bh[nt][0], Bh[nt][1]);
                mma_bf16(c, l0.x, l1.x, l0.y, l1.y, Bh[nt][0], Bh[nt][1]);
                mma_bf16(c, h0.x, h1.x, h0.y, h1.y, Bl[nt][0], Bl[nt][1]);
            }
        }
    }

    // ---- epilogue: write partials ----
    float* Pz = P + (size_t)blockIdx.z * M * Npad;
    const int mbase = m0 + wm * 64;
    const int nbase = n0 + wn * 32;
#pragma unroll
    for (int mt = 0; mt < 4; mt++) {
#pragma unroll
        for (int nt = 0; nt < 4; nt++) {
            float* c = acc[mt][nt];
            int r = mbase + mt * 16 + g;
            int cc = nbase + nt * 8 + tig * 2;
            *(float2*)&Pz[(size_t)r * Npad + cc]       = make_float2(c[0], c[1]);
            *(float2*)&Pz[(size_t)(r + 8) * Npad + cc] = make_float2(c[2], c[3]);
        }
    }
}

// ---------------- split-K reduces with fused epilogues + plane writes -----------
// conv: act1 logical row b (256), col k = col*49 + hw (6272). One thread per
// (b, pair j): k0=2j, k1=2j+1.
__global__ void reduce_conv(const float* __restrict__ part,
                            const float* __restrict__ bias) {
    int idx = blockIdx.x * blockDim.x + threadIdx.x;
    if (idx >= 256 * 3136) return;
    const int S = 12544 * 128;
    int b = idx >> 11;          // /2048? no: 3136 per b
    b = idx / 3136;
    int j = idx - b * 3136;
    float v[2];
#pragma unroll
    for (int e = 0; e < 2; e++) {
        int k = 2 * j + e;
        int col = k / 49, hw = k - col * 49;
        int m = b * 49 + hw;
        int p = m * 128 + col;
        v[e] = part[p] + part[S + p] + part[2 * S + p] + bias[col];
    }
    uint32_t hi, lo;
    pack_pair(v[0], v[1], hi, lo);
    g_a1h[idx] = hi;
    g_a1l[idx] = lo;
}

__global__ void reduce_fc1(const float* __restrict__ part,
                           const float* __restrict__ bias) {
    int idx = blockIdx.x * blockDim.x + threadIdx.x;
    if (idx >= 256 * 2048) return;
    const int S = 256 * 4096;
    int m = idx >> 11;
    int j = idx & 2047;
    int p = (m << 12) + 2 * j;
    float v[2];
#pragma unroll
    for (int e = 0; e < 2; e++) {
        float s = part[p + e] + part[S + p + e] + part[2 * S + p + e]
                + part[3 * S + p + e] + bias[2 * j + e];
        v[e] = (s >= 0.f) ? s : 0.1f * s;
    }
    uint32_t hi, lo;
    pack_pair(v[0], v[1], hi, lo);
    g_h1h[idx] = hi;
    g_h1l[idx] = lo;
}

__global__ void reduce_fc2(const float* __restrict__ part,
                           const float* __restrict__ bias) {
    int idx = blockIdx.x * blockDim.x + threadIdx.x;
    if (idx >= 256 * 1470) return;
    int m = idx / 1470, n = idx - m * 1470;
    float v = 0.f;
#pragma unroll
    for (int s = 0; s < 12; s++) v += part[(size_t)s * 256 * 1536 + m * 1536 + n];
    v += bias[n];
    g_h2[idx] = 1.f / (1.f + expf(-v));
}

// ---------------- decode: h2 -> boxes / conf / labels ---------------------------
__global__ void decode_kernel() {
    int idx = blockIdx.x * blockDim.x + threadIdx.x;
    if (idx >= BATCH * NBOX) return;
    int b = idx / NBOX, n = idx % NBOX;
    int cell = n >> 1;
    int gi = cell / 7, gj = cell % 7;
    const float* h = g_h2 + (size_t)b * 1470;

    float bx = h[n * 4 + 0], by = h[n * 4 + 1];
    float bw = h[n * 4 + 2], bh = h[n * 4 + 3];
    float cx = bx * 64.f + gi * 64.f;
    float cy = by * 64.f + gj * 64.f;
    float w  = bw * 448.f;
    float hh = bh * 448.f;
    float x1 = fminf(fmaxf(cx - 0.5f * w,  0.f), 448.f);
    float y1 = fminf(fmaxf(cy - 0.5f * hh, 0.f), 448.f);
    float x2 = fminf(fmaxf(cx + 0.5f * w,  0.f), 448.f);
    float y2 = fminf(fmaxf(cy + 0.5f * hh, 0.f), 448.f);

    g_boxes[idx * 4 + 0] = x1;
    g_boxes[idx * 4 + 1] = y1;
    g_boxes[idx * 4 + 2] = x2;
    g_boxes[idx * 4 + 3] = y2;
    g_conf[idx] = h[392 + n];

    const float* cl = h + 490 + cell * 20;
    float best = cl[0];
    int lab = 0;
#pragma unroll
    for (int c = 1; c < 20; c++) {
        float v = cl[c];
        if (v > best) { best = v; lab = c; }  // first max wins (matches jnp.argmax)
    }
    g_labels[idx] = lab;
}

// ---------------- NMS: one block per image --------------------------------------
__global__ void __launch_bounds__(128)
nms_kernel(float* __restrict__ out, int out_size) {
    int b = blockIdx.x;
    int t = threadIdx.x;

    __shared__ float sc[NBOX], sx1[NBOX], sy1[NBOX], sx2[NBOX], sy2[NBOX];
    __shared__ int   sl[NBOX], order[NBOX];
    __shared__ float oc[NBOX], ox1[NBOX], oy1[NBOX], ox2[NBOX], oy2[NBOX], oarea[NBOX];
    __shared__ int   ol[NBOX];
    __shared__ unsigned char keep[NBOX];

    if (t < NBOX) {
        int g = b * NBOX + t;
        sc[t]  = g_conf[g];
        sl[t]  = g_labels[g];
        sx1[t] = g_boxes[g * 4 + 0];
        sy1[t] = g_boxes[g * 4 + 1];
        sx2[t] = g_boxes[g * 4 + 2];
        sy2[t] = g_boxes[g * 4 + 3];
    }
    __syncthreads();

    if (t < NBOX) {
        float c = sc[t];
        int r = 0;
        for (int j = 0; j < NBOX; j++) {
            float cj = sc[j];
            r += (cj > c) || (cj == c && j < t);
        }
        order[r] = t;
    }
    __syncthreads();

    if (t < NBOX) {
        int s = order[t];
        oc[t] = sc[s];  ol[t] = sl[s];
        ox1[t] = sx1[s]; oy1[t] = sy1[s];
        ox2[t] = sx2[s]; oy2[t] = sy2[s];
        oarea[t] = fmaxf(ox2[t] - ox1[t], 0.f) * fmaxf(oy2[t] - oy1[t], 0.f);
        keep[t] = (oc[t] > 0.1f) ? (unsigned char)1 : (unsigned char)0;
    }
    __syncthreads();

    for (int i = 0; i < NBOX; i++) {
        if (keep[i] && t < NBOX && t > i) {
            float ix1 = fmaxf(ox1[i], ox1[t]);
            float iy1 = fmaxf(oy1[i], oy1[t]);
            float ix2 = fminf(ox2[i], ox2[t]);
            float iy2 = fminf(oy2[i], oy2[t]);
            float inter = fmaxf(ix2 - ix1, 0.f) * fmaxf(iy2 - iy1, 0.f);
            float uni = oarea[i] + oarea[t] - inter;
            float iou = (uni > 0.f) ? (inter / uni) : 0.f;
            if (iou > 0.7f) keep[t] = 0;
        }
        __syncthreads();
    }

    if (t == 0) {
        unsigned char used[NBOX];
        for (int j = 0; j < NBOX; j++) used[j] = 0;
        const int BK4 = BATCH * KTOP * 4;
        const int BK  = BATCH * KTOP;
        for (int k = 0; k < KTOP; k++) {
            float best = -2.f;
            int bi = 0;
            for (int j = 0; j < NBOX; j++) {
                if (used[j]) continue;
                float s = keep[j] ? oc[j] : -1.0f;
                if (s > best) { best = s; bi = j; }
            }
            used[bi] = 1;
            bool valid = best > 0.1f;
            int ob = (b * KTOP + k) * 4;
            if (ob + 3 < out_size) {
                out[ob + 0] = valid ? ox1[bi] : 0.f;
                out[ob + 1] = valid ? oy1[bi] : 0.f;
                out[ob + 2] = valid ? ox2[bi] : 0.f;
                out[ob + 3] = valid ? oy2[bi] : 0.f;
            }
            int ol_idx = BK4 + b * KTOP + k;
            if (ol_idx < out_size) out[ol_idx] = valid ? (float)ol[bi] : 0.f;
            int oc_idx = BK4 + BK + b * KTOP + k;
            if (oc_idx < out_size) out[oc_idx] = valid ? oc[bi] : 0.f;
        }
    }
}

// ---------------- launch ---------------------------------------------------------
extern "C" void kernel_launch(void* const* d_in, const int* in_sizes, int n_in,
                              void* d_out, int out_size) {
    const float* x      = (const float*)d_in[0];
    const float* conv_w = (const float*)d_in[1];
    const float* conv_b = (const float*)d_in[2];
    const float* fc1_w  = (const float*)d_in[3];
    const float* fc1_b  = (const float*)d_in[4];
    const float* fc2_w  = (const float*)d_in[5];
    const float* fc2_b  = (const float*)d_in[6];
    float* out = (float*)d_out;

    uint32_t *A0h, *A0l, *a1h, *a1l, *h1h, *h1l;
    float *part;
    cudaGetSymbolAddress((void**)&A0h, g_A0h);
    cudaGetSymbolAddress((void**)&A0l, g_A0l);
    cudaGetSymbolAddress((void**)&a1h, g_a1h);
    cudaGetSymbolAddress((void**)&a1l, g_a1l);
    cudaGetSymbolAddress((void**)&h1h, g_h1h);
    cudaGetSymbolAddress((void**)&h1l, g_h1l);
    cudaGetSymbolAddress((void**)&part, g_part);

    cudaFuncSetAttribute(gemm_mma, cudaFuncAttributeMaxDynamicSharedMemorySize,
                         DSMEM_BYTES);

    // 1. gather subsampled input -> A0 bf16x2 hi/lo planes
    gather_kernel<<<dim3(20, 256), 256>>>(x);

    // 2. conv GEMM: (12544 x 1280) * (128 x 1280)^T, split-K=3 -> 294 CTAs
    gemm_mma<<<dim3(1, 98, 3), 256, DSMEM_BYTES>>>(A0h, A0l, conv_w, part,
                                                   12544, 128, 1280, 432, 128);
    reduce_conv<<<(256 * 3136 + 255) / 256, 256>>>(part, conv_b);

    // 3. fc1 GEMM: (256 x 6272) * (4096 x 6272)^T, split-K=4 -> 256 CTAs
    gemm_mma<<<dim3(32, 2, 4), 256, DSMEM_BYTES>>>(a1h, a1l, fc1_w, part,
                                                   256, 4096, 6272, 1568, 4096);
    reduce_fc1<<<(256 * 2048 + 255) / 256, 256>>>(part, fc1_b);

    // 4. fc2 GEMM: (256 x 4096) * (1470 x 4096)^T, split-K=12 -> 288 CTAs
    gemm_mma<<<dim3(12, 2, 12), 256, DSMEM_BYTES>>>(h1h, h1l, fc2_w, part,
                                                    256, 1470, 4096, 352, 1536);
    reduce_fc2<<<(256 * 1470 + 255) / 256, 256>>>(part, fc2_b);

    // 5. decode + NMS
    decode_kernel<<<(BATCH * NBOX + 255) / 256, 256>>>();
    nms_kernel<<<BATCH, 128>>>(out, out_size);
}

// round 17
// speedup vs baseline: 1.0453x; 1.0452x over previous
#include <cuda_runtime.h>
#include <math.h>
#include <cstdint>

#define BATCH 256
#define NBOX 98
#define KTOP 10

// ---------------- scratch (static device globals; no allocation) ----------------
// Activation operands as bf16x2 hi/lo planes in PERMUTED fragment-slot order:
// within each 8-pair group, pair j sits at slot (j&~7) + 2*(j&3) + ((j>>2)&1).
// Lane tig's fragment words (pairs tig, tig+4 of a group) are thus adjacent 8B.
__device__ uint32_t g_A0h[12544 * 640], g_A0l[12544 * 640];   // gathered input
__device__ uint32_t g_a1h[256 * 3136],  g_a1l[256 * 3136];    // act1 (fc1 A)
__device__ uint32_t g_h1h[256 * 2048],  g_h1l[256 * 2048];    // h1 (fc2 A)
__device__ float g_part[3 * 12544 * 128];  // split-K partials (max: conv)
__device__ float g_h2[BATCH * 1470];
__device__ float g_boxes[BATCH * NBOX * 4];
__device__ float g_conf[BATCH * NBOX];
__device__ int   g_labels[BATCH * NBOX];

// ---------------- helpers -------------------------------------------------------
__device__ __forceinline__ uint32_t smem_u32(const void* p) {
    uint32_t a;
    asm("{ .reg .u64 t; cvta.to.shared.u64 t, %1; cvt.u32.u64 %0, t; }"
        : "=r"(a) : "l"(p));
    return a;
}
__device__ __forceinline__ void cp8(uint32_t dst, const void* src) {
    asm volatile("cp.async.ca.shared.global [%0], [%1], 8;" :: "r"(dst), "l"(src));
}
#define CP_COMMIT() asm volatile("cp.async.commit_group;" ::: "memory")
#define CP_WAIT2()  asm volatile("cp.async.wait_group 2;" ::: "memory")

// ---- 3xBF16 split helpers (hi = truncate to bf16; lo = rn-bf16(a - hi)) ----
__device__ __forceinline__ float sub_hi(float a) {
    return a - __uint_as_float(__float_as_uint(a) & 0xFFFF0000u);
}
__device__ __forceinline__ uint32_t prmt_hi(uint32_t x, uint32_t y) {
    uint32_t r;
    asm("prmt.b32 %0, %1, %2, 0x7632;" : "=r"(r) : "r"(x), "r"(y));
    return r;
}
__device__ __forceinline__ uint32_t cvt_bf16x2(float h, float l) {
    uint32_t r;
    asm("cvt.rn.bf16x2.f32 %0, %1, %2;" : "=r"(r) : "f"(h), "f"(l));
    return r;
}
__device__ __forceinline__ void pack_pair(float a0, float a1,
                                          uint32_t& hi, uint32_t& lo) {
    hi = prmt_hi(__float_as_uint(a0), __float_as_uint(a1));
    lo = cvt_bf16x2(sub_hi(a1), sub_hi(a0));
}
// permuted slot for pair index J
__device__ __forceinline__ int pslot(int J) {
    return (J & ~7) + 2 * (J & 3) + ((J >> 2) & 1);
}

__device__ __forceinline__ void mma_bf16(float* c, uint32_t a0, uint32_t a1,
                                         uint32_t a2, uint32_t a3,
                                         uint32_t b0, uint32_t b1) {
    asm volatile(
        "mma.sync.aligned.m16n8k16.row.col.f32.bf16.bf16.f32 "
        "{%0,%1,%2,%3}, {%4,%5,%6,%7}, {%8,%9}, {%0,%1,%2,%3};"
        : "+f"(c[0]), "+f"(c[1]), "+f"(c[2]), "+f"(c[3])
        : "r"(a0), "r"(a1), "r"(a2), "r"(a3), "r"(b0), "r"(b1));
}

// ---------------- gather: x[:, :, ::2, ::2] -> A0 planes (permuted) --------------
__global__ void gather_kernel(const float* __restrict__ x) {
    __shared__ float tile[64][50];
    const int b  = blockIdx.y;
    const int c0 = blockIdx.x * 64;
    const int t  = threadIdx.x;
    for (int lin = t; lin < 64 * 49; lin += 256) {
        int c = lin / 49, hw = lin % 49;
        tile[c][hw] =
            x[((size_t)(b * 1280 + c0 + c) * 14 + (hw / 7) * 2) * 14 + (hw % 7) * 2];
    }
    __syncthreads();
    for (int lin = t; lin < 32 * 49; lin += 256) {
        int hw = lin >> 5, jl = lin & 31;
        uint32_t hi, lo;
        pack_pair(tile[2 * jl][hw], tile[2 * jl + 1][hw], hi, lo);
        int J = (c0 >> 1) + jl;
        size_t w = ((size_t)b * 49 + hw) * 640 + pslot(J);
        g_A0h[w] = hi;
        g_A0l[w] = lo;
    }
}

// ---------------- 3xBF16 mma.sync GEMM, permuted A planes, BK=16, 4 stages -------
// CTA tile 128x128; 8 warps: 2(m) x 4(n); warp tile 64x32.
// smem stage (4096 words): A-hi [0,1024), A-lo [1024,2048), B raw fp32 [2048,4096).
// A seg s: word s*64 + lane*2 + {0,1} = fragment words (pairs tig, tig+4).
// B seg: seg*128 + lane*4, k = {2tig,2tig+1,2tig+8,2tig+9}.
#define STAGE_WORDS 4096
#define DSMEM_BYTES (4 * STAGE_WORDS * 4)

__device__ __forceinline__ void load_stage(
    uint32_t su, int buf,
    const uint32_t* __restrict__ Ah, const uint32_t* __restrict__ Al,
    const float* __restrict__ B,
    int Kp, int K, const int* rowA, const int* rowB, int kb,
    int wid, int lane, int tig)
{
    uint32_t base = su + buf * (STAGE_WORDS * 4);
    const int jb = kb >> 1;        // group base in pair units (multiple of 8)
#pragma unroll
    for (int i = 0; i < 2; i++) {
        int seg = wid + i * 8;
        uint32_t da = base + (uint32_t)(seg * 64 + lane * 2) * 4;
        const size_t ga = (size_t)rowA[i] * Kp + jb + 2 * tig;
        cp8(da,        Ah + ga);       // hi: pairs {tig, tig+4} (permuted adjacency)
        cp8(da + 4096, Al + ga);       // lo
        uint32_t db = base + (uint32_t)(2048 + seg * 128 + lane * 4) * 4;
        const float* sb = B + (size_t)rowB[i] * K + kb + 2 * tig;
        cp8(db,     sb);
        cp8(db + 8, sb + 8);
    }
}

__global__ void __launch_bounds__(256, 2)
gemm_mma(const uint32_t* __restrict__ Ah, const uint32_t* __restrict__ Al,
         const float* __restrict__ B,
         float* __restrict__ P, int M, int N, int K, int kc, int Npad) {
    extern __shared__ __align__(16) uint32_t sm[];
    const uint32_t su = smem_u32(sm);

    const int tid  = threadIdx.x;
    const int wid  = tid >> 5;
    const int lane = tid & 31;
    const int g    = lane >> 2;
    const int tig  = lane & 3;
    const int wm   = wid >> 2;
    const int wn   = wid & 3;

    const int Kp = K >> 1;
    const int m0 = blockIdx.y * 128;
    const int n0 = blockIdx.x * 128;
    const int k0 = blockIdx.z * kc;
    const int nstages = (min(kc, K - k0)) >> 4;

    int rowA[2], rowB[2];
#pragma unroll
    for (int i = 0; i < 2; i++) {
        int sA = wid + i * 8;
        rowA[i] = m0 + (sA >> 1) * 16 + (sA & 1) * 8 + g;
        int nr = n0 + (wid + i * 8) * 8 + g;
        rowB[i] = (nr < N) ? nr : (N - 1);
    }

    float acc[4][4][4];
#pragma unroll
    for (int a = 0; a < 4; a++)
#pragma unroll
        for (int b = 0; b < 4; b++)
#pragma unroll
            for (int c = 0; c < 4; c++) acc[a][b][c] = 0.f;

    // prologue: issue stages 0..2
#pragma unroll
    for (int s = 0; s < 3; s++) {
        if (s < nstages) load_stage(su, s, Ah, Al, B, Kp, K, rowA, rowB,
                                    k0 + s * 16, wid, lane, tig);
        CP_COMMIT();
    }

    for (int t = 0; t < nstages; t++) {
        CP_WAIT2();
        __syncthreads();
        if (t + 3 < nstages)
            load_stage(su, (t + 3) & 3, Ah, Al, B, Kp, K, rowA, rowB,
                       k0 + (t + 3) * 16, wid, lane, tig);
        CP_COMMIT();

        const uint32_t* sb = sm + (t & 3) * STAGE_WORDS;

        // ---- B fragments: raw fp32 -> hi via PRMT, lo via FADD+CVT ----
        uint32_t Bh[4][2], Bl[4][2];
#pragma unroll
        for (int nt = 0; nt < 4; nt++) {
            uint4 raw = *(const uint4*)&sb[2048 + (wn * 4 + nt) * 128 + lane * 4];
            const float* f = (const float*)&raw;
            const uint32_t* u = (const uint32_t*)&raw;
            Bh[nt][0] = prmt_hi(u[0], u[1]);
            Bh[nt][1] = prmt_hi(u[2], u[3]);
            Bl[nt][0] = cvt_bf16x2(sub_hi(f[1]), sub_hi(f[0]));
            Bl[nt][1] = cvt_bf16x2(sub_hi(f[3]), sub_hi(f[2]));
        }

#pragma unroll
        for (int mt = 0; mt < 4; mt++) {
            int s0 = (wm * 4 + mt) * 2;
            // A fragments: direct LDS.64 from planes, zero ALU
            uint2 h0 = *(const uint2*)&sb[s0 * 64 + lane * 2];          // row g
            uint2 h1 = *(const uint2*)&sb[(s0 + 1) * 64 + lane * 2];    // row g+8
            uint2 l0 = *(const uint2*)&sb[1024 + s0 * 64 + lane * 2];
            uint2 l1 = *(const uint2*)&sb[1024 + (s0 + 1) * 64 + lane * 2];
#pragma unroll
            for (int nt = 0; nt < 4; nt++) {
                float* c = acc[mt][nt];
                mma_bf16(c, h0.x, h1.x, h0.y, h1.y, Bh[nt][0], Bh[nt][1]);
                mma_bf16(c, l0.x, l1.x, l0.y, l1.y, Bh[nt][0], Bh[nt][1]);
                mma_bf16(c, h0.x, h1.x, h0.y, h1.y, Bl[nt][0], Bl[nt][1]);
            }
        }
    }

    // ---- epilogue: write partials ----
    float* Pz = P + (size_t)blockIdx.z * M * Npad;
    const int mbase = m0 + wm * 64;
    const int nbase = n0 + wn * 32;
#pragma unroll
    for (int mt = 0; mt < 4; mt++) {
#pragma unroll
        for (int nt = 0; nt < 4; nt++) {
            float* c = acc[mt][nt];
            int r = mbase + mt * 16 + g;
            int cc = nbase + nt * 8 + tig * 2;
            *(float2*)&Pz[(size_t)r * Npad + cc]       = make_float2(c[0], c[1]);
            *(float2*)&Pz[(size_t)(r + 8) * Npad + cc] = make_float2(c[2], c[3]);
        }
    }
}

// ---------------- split-K reduces with fused epilogues + permuted plane writes ---
__global__ void reduce_conv(const float* __restrict__ part,
                            const float* __restrict__ bias) {
    int idx = blockIdx.x * blockDim.x + threadIdx.x;
    if (idx >= 256 * 3136) return;
    const int S = 12544 * 128;
    int b = idx / 3136;
    int j = idx - b * 3136;
    float v[2];
#pragma unroll
    for (int e = 0; e < 2; e++) {
        int k = 2 * j + e;
        int col = k / 49, hw = k - col * 49;
        int m = b * 49 + hw;
        int p = m * 128 + col;
        v[e] = part[p] + part[S + p] + part[2 * S + p] + bias[col];
    }
    uint32_t hi, lo;
    pack_pair(v[0], v[1], hi, lo);
    size_t w = (size_t)b * 3136 + pslot(j);
    g_a1h[w] = hi;
    g_a1l[w] = lo;
}

__global__ void reduce_fc1(const float* __restrict__ part,
                           const float* __restrict__ bias) {
    int idx = blockIdx.x * blockDim.x + threadIdx.x;
    if (idx >= 256 * 2048) return;
    const int S = 256 * 4096;
    int m = idx >> 11;
    int j = idx & 2047;
    int p = (m << 12) + 2 * j;
    float v[2];
#pragma unroll
    for (int e = 0; e < 2; e++) {
        float s = part[p + e] + part[S + p + e] + part[2 * S + p + e]
                + part[3 * S + p + e] + bias[2 * j + e];
        v[e] = (s >= 0.f) ? s : 0.1f * s;
    }
    uint32_t hi, lo;
    pack_pair(v[0], v[1], hi, lo);
    size_t w = ((size_t)m << 11) + pslot(j);
    g_h1h[w] = hi;
    g_h1l[w] = lo;
}

__global__ void reduce_fc2(const float* __restrict__ part,
                           const float* __restrict__ bias) {
    int idx = blockIdx.x * blockDim.x + threadIdx.x;
    if (idx >= 256 * 1470) return;
    int m = idx / 1470, n = idx - m * 1470;
    float v = 0.f;
#pragma unroll
    for (int s = 0; s < 12; s++) v += part[(size_t)s * 256 * 1536 + m * 1536 + n];
    v += bias[n];
    g_h2[idx] = 1.f / (1.f + expf(-v));
}

// ---------------- decode: h2 -> boxes / conf / labels ---------------------------
__global__ void decode_kernel() {
    int idx = blockIdx.x * blockDim.x + threadIdx.x;
    if (idx >= BATCH * NBOX) return;
    int b = idx / NBOX, n = idx % NBOX;
    int cell = n >> 1;
    int gi = cell / 7, gj = cell % 7;
    const float* h = g_h2 + (size_t)b * 1470;

    float bx = h[n * 4 + 0], by = h[n * 4 + 1];
    float bw = h[n * 4 + 2], bh = h[n * 4 + 3];
    float cx = bx * 64.f + gi * 64.f;
    float cy = by * 64.f + gj * 64.f;
    float w  = bw * 448.f;
    float hh = bh * 448.f;
    float x1 = fminf(fmaxf(cx - 0.5f * w,  0.f), 448.f);
    float y1 = fminf(fmaxf(cy - 0.5f * hh, 0.f), 448.f);
    float x2 = fminf(fmaxf(cx + 0.5f * w,  0.f), 448.f);
    float y2 = fminf(fmaxf(cy + 0.5f * hh, 0.f), 448.f);

    g_boxes[idx * 4 + 0] = x1;
    g_boxes[idx * 4 + 1] = y1;
    g_boxes[idx * 4 + 2] = x2;
    g_boxes[idx * 4 + 3] = y2;
    g_conf[idx] = h[392 + n];

    const float* cl = h + 490 + cell * 20;
    float best = cl[0];
    int lab = 0;
#pragma unroll
    for (int c = 1; c < 20; c++) {
        float v = cl[c];
        if (v > best) { best = v; lab = c; }  // first max wins (matches jnp.argmax)
    }
    g_labels[idx] = lab;
}

// ---------------- NMS: one block per image --------------------------------------
__global__ void __launch_bounds__(128)
nms_kernel(float* __restrict__ out, int out_size) {
    int b = blockIdx.x;
    int t = threadIdx.x;

    __shared__ float sc[NBOX], sx1[NBOX], sy1[NBOX], sx2[NBOX], sy2[NBOX];
    __shared__ int   sl[NBOX], order[NBOX];
    __shared__ float oc[NBOX], ox1[NBOX], oy1[NBOX], ox2[NBOX], oy2[NBOX], oarea[NBOX];
    __shared__ int   ol[NBOX];
    __shared__ unsigned char keep[NBOX];

    if (t < NBOX) {
        int g = b * NBOX + t;
        sc[t]  = g_conf[g];
        sl[t]  = g_labels[g];
        sx1[t] = g_boxes[g * 4 + 0];
        sy1[t] = g_boxes[g * 4 + 1];
        sx2[t] = g_boxes[g * 4 + 2];
        sy2[t] = g_boxes[g * 4 + 3];
    }
    __syncthreads();

    if (t < NBOX) {
        float c = sc[t];
        int r = 0;
        for (int j = 0; j < NBOX; j++) {
            float cj = sc[j];
            r += (cj > c) || (cj == c && j < t);
        }
        order[r] = t;
    }
    __syncthreads();

    if (t < NBOX) {
        int s = order[t];
        oc[t] = sc[s];  ol[t] = sl[s];
        ox1[t] = sx1[s]; oy1[t] = sy1[s];
        ox2[t] = sx2[s]; oy2[t] = sy2[s];
        oarea[t] = fmaxf(ox2[t] - ox1[t], 0.f) * fmaxf(oy2[t] - oy1[t], 0.f);
        keep[t] = (oc[t] > 0.1f) ? (unsigned char)1 : (unsigned char)0;
    }
    __syncthreads();

    for (int i = 0; i < NBOX; i++) {
        if (keep[i] && t < NBOX && t > i) {
            float ix1 = fmaxf(ox1[i], ox1[t]);
            float iy1 = fmaxf(oy1[i], oy1[t]);
            float ix2 = fminf(ox2[i], ox2[t]);
            float iy2 = fminf(oy2[i], oy2[t]);
            float inter = fmaxf(ix2 - ix1, 0.f) * fmaxf(iy2 - iy1, 0.f);
            float uni = oarea[i] + oarea[t] - inter;
            float iou = (uni > 0.f) ? (inter / uni) : 0.f;
            if (iou > 0.7f) keep[t] = 0;
        }
        __syncthreads();
    }

    if (t == 0) {
        unsigned char used[NBOX];
        for (int j = 0; j < NBOX; j++) used[j] = 0;
        const int BK4 = BATCH * KTOP * 4;
        const int BK  = BATCH * KTOP;
        for (int k = 0; k < KTOP; k++) {
            float best = -2.f;
            int bi = 0;
            for (int j = 0; j < NBOX; j++) {
                if (used[j]) continue;
                float s = keep[j] ? oc[j] : -1.0f;
                if (s > best) { best = s; bi = j; }
            }
            used[bi] = 1;
            bool valid = best > 0.1f;
            int ob = (b * KTOP + k) * 4;
            if (ob + 3 < out_size) {
                out[ob + 0] = valid ? ox1[bi] : 0.f;
                out[ob + 1] = valid ? oy1[bi] : 0.f;
                out[ob + 2] = valid ? ox2[bi] : 0.f;
                out[ob + 3] = valid ? oy2[bi] : 0.f;
            }
            int ol_idx = BK4 + b * KTOP + k;
            if (ol_idx < out_size) out[ol_idx] = valid ? (float)ol[bi] : 0.f;
            int oc_idx = BK4 + BK + b * KTOP + k;
            if (oc_idx < out_size) out[oc_idx] = valid ? oc[bi] : 0.f;
        }
    }
}

// ---------------- launch ---------------------------------------------------------
extern "C" void kernel_launch(void* const* d_in, const int* in_sizes, int n_in,
                              void* d_out, int out_size) {
    const float* x      = (const float*)d_in[0];
    const float* conv_w = (const float*)d_in[1];
    const float* conv_b = (const float*)d_in[2];
    const float* fc1_w  = (const float*)d_in[3];
    const float* fc1_b  = (const float*)d_in[4];
    const float* fc2_w  = (const float*)d_in[5];
    const float* fc2_b  = (const float*)d_in[6];
    float* out = (float*)d_out;

    uint32_t *A0h, *A0l, *a1h, *a1l, *h1h, *h1l;
    float *part;
    cudaGetSymbolAddress((void**)&A0h, g_A0h);
    cudaGetSymbolAddress((void**)&A0l, g_A0l);
    cudaGetSymbolAddress((void**)&a1h, g_a1h);
    cudaGetSymbolAddress((void**)&a1l, g_a1l);
    cudaGetSymbolAddress((void**)&h1h, g_h1h);
    cudaGetSymbolAddress((void**)&h1l, g_h1l);
    cudaGetSymbolAddress((void**)&part, g_part);

    cudaFuncSetAttribute(gemm_mma, cudaFuncAttributeMaxDynamicSharedMemorySize,
                         DSMEM_BYTES);

    // 1. gather subsampled input -> A0 bf16x2 hi/lo planes (permuted)
    gather_kernel<<<dim3(20, 256), 256>>>(x);

    // 2. conv GEMM: (12544 x 1280) * (128 x 1280)^T, split-K=3 -> 294 CTAs
    gemm_mma<<<dim3(1, 98, 3), 256, DSMEM_BYTES>>>(A0h, A0l, conv_w, part,
                                                   12544, 128, 1280, 432, 128);
    reduce_conv<<<(256 * 3136 + 255) / 256, 256>>>(part, conv_b);

    // 3. fc1 GEMM: (256 x 6272) * (4096 x 6272)^T, split-K=4 -> 256 CTAs
    gemm_mma<<<dim3(32, 2, 4), 256, DSMEM_BYTES>>>(a1h, a1l, fc1_w, part,
                                                   256, 4096, 6272, 1568, 4096);
    reduce_fc1<<<(256 * 2048 + 255) / 256, 256>>>(part, fc1_b);

    // 4. fc2 GEMM: (256 x 4096) * (1470 x 4096)^T, split-K=12 -> 288 CTAs
    gemm_mma<<<dim3(12, 2, 12), 256, DSMEM_BYTES>>>(h1h, h1l, fc2_w, part,
                                                    256, 1470, 4096, 352, 1536);
    reduce_fc2<<<(256 * 1470 + 255) / 256, 256>>>(part, fc2_b);

    // 5. decode + NMS
    decode_kernel<<<(BATCH * NBOX + 255) / 256, 256>>>();
    nms_kernel<<<BATCH, 128>>>(out, out_size);
}